// round 2
// baseline (speedup 1.0000x reference)
#include <cuda_runtime.h>
#include <math.h>

// Problem constants
#define B_    16
#define CIN   128
#define COUT  256
#define HW    56
#define HWHW  (HW*HW)        // 3136
#define KTAPS 9

// Tiling
#define CI_T    8            // input-channel chunk in smem
#define COUT_T  32           // cout tile per block
#define TH      8            // spatial tile 8x8
#define TW      8
#define HALO    10           // TH+2
#define NTHREADS 128

// Scratch (allocation-free: device globals)
// weights packed: w[(ci*9+tap)*COUT + co] = {cp*co_, sp*co_, cp*so_, sp*so_}
static __device__ float4 g_w[CIN * KTAPS * COUT];             // 4.7 MB
// input packed: cs[((b*CIN+ci)*HWHW) + h*HW + w] = {cos x, sin x}
static __device__ float2 g_cs[B_ * CIN * HWHW];               // 51.4 MB

__global__ void prep_weights_kernel(const float* __restrict__ probe,
                                    const float* __restrict__ outang) {
    int idx = blockIdx.x * blockDim.x + threadIdx.x;
    int n = CIN * COUT * KTAPS;
    if (idx >= n) return;
    // probe layout: (CIN, COUT, 3, 3) flattened
    int tap = idx % KTAPS;
    int co  = (idx / KTAPS) % COUT;
    int ci  = idx / (KTAPS * COUT);
    float p = probe[idx];
    float o = outang[idx];
    float cp, sp, c_o, s_o;
    sincosf(p, &sp, &cp);
    sincosf(o, &s_o, &c_o);
    g_w[(ci * KTAPS + tap) * COUT + co] =
        make_float4(cp * c_o, sp * c_o, cp * s_o, sp * s_o);
}

__global__ void prep_input_kernel(const float* __restrict__ x) {
    int idx = blockIdx.x * blockDim.x + threadIdx.x;
    if (idx >= B_ * CIN * HWHW) return;
    float v = x[idx];
    float s, c;
    sincosf(v, &s, &c);
    g_cs[idx] = make_float2(c, s);
}

// Direct conv. Grid: (49 spatial tiles, 8 cout blocks, 16 batches).
// Each block: 32 couts x 64 pixels. Each thread: 4 couts x 4 pixels (2x2).
__global__ __launch_bounds__(NTHREADS)
void ring_conv_kernel(float* __restrict__ out) {
    __shared__ float4 sW[CI_T][KTAPS][COUT_T];   // 36,864 B
    __shared__ float2 sI[CI_T][HALO][HALO];      //  6,400 B

    const int tid = threadIdx.x;
    const int tile = blockIdx.x;           // 0..48
    const int th = tile / 7, tw = tile % 7;
    const int cb = blockIdx.y * COUT_T;
    const int b  = blockIdx.z;
    const int h0 = th * TH - 1, w0 = tw * TW - 1;   // halo origin

    const int pg  = tid & 15;              // pixel group: 4x4 grid of 2x2 blocks
    const int cg  = tid >> 4;              // cout group: 0..7 (4 couts each)
    const int pgh = pg >> 2, pgw = pg & 3;

    float accRe[4][4];
    float accIm[4][4];
    #pragma unroll
    for (int p = 0; p < 4; p++)
        #pragma unroll
        for (int j = 0; j < 4; j++) { accRe[p][j] = 0.f; accIm[p][j] = 0.f; }

    const float2* __restrict__ csb = g_cs + (size_t)b * CIN * HWHW;

    for (int ci0 = 0; ci0 < CIN; ci0 += CI_T) {
        __syncthreads();
        // weights: CI_T*9*32 = 2304 float4s
        #pragma unroll
        for (int idx = tid; idx < CI_T * KTAPS * COUT_T; idx += NTHREADS) {
            int ci_l = idx / (KTAPS * COUT_T);
            int rem  = idx % (KTAPS * COUT_T);
            int tap  = rem / COUT_T;
            int col  = rem % COUT_T;
            sW[ci_l][tap][col] = g_w[((ci0 + ci_l) * KTAPS + tap) * COUT + cb + col];
        }
        // input halo: CI_T*100 = 800 float2s
        #pragma unroll
        for (int idx = tid; idx < CI_T * HALO * HALO; idx += NTHREADS) {
            int ci_l = idx / (HALO * HALO);
            int rem  = idx % (HALO * HALO);
            int r = rem / HALO, c = rem % HALO;
            int h = h0 + r, w = w0 + c;
            float2 v = make_float2(0.f, 0.f);
            if ((unsigned)h < HW && (unsigned)w < HW)
                v = csb[(ci0 + ci_l) * HWHW + h * HW + w];
            sI[ci_l][r][c] = v;
        }
        __syncthreads();

        for (int ci_l = 0; ci_l < CI_T; ci_l++) {
            #pragma unroll
            for (int kh = 0; kh < 3; kh++) {
                #pragma unroll
                for (int kw = 0; kw < 3; kw++) {
                    float2 iv[4];
                    iv[0] = sI[ci_l][pgh * 2 + kh    ][pgw * 2 + kw    ];
                    iv[1] = sI[ci_l][pgh * 2 + kh    ][pgw * 2 + kw + 1];
                    iv[2] = sI[ci_l][pgh * 2 + kh + 1][pgw * 2 + kw    ];
                    iv[3] = sI[ci_l][pgh * 2 + kh + 1][pgw * 2 + kw + 1];
                    float4 w4[4];
                    #pragma unroll
                    for (int j = 0; j < 4; j++)
                        w4[j] = sW[ci_l][kh * 3 + kw][cg * 4 + j];
                    #pragma unroll
                    for (int p = 0; p < 4; p++) {
                        #pragma unroll
                        for (int j = 0; j < 4; j++) {
                            accRe[p][j] = fmaf(iv[p].x, w4[j].x,
                                          fmaf(iv[p].y, w4[j].y, accRe[p][j]));
                            accIm[p][j] = fmaf(iv[p].x, w4[j].z,
                                          fmaf(iv[p].y, w4[j].w, accIm[p][j]));
                        }
                    }
                }
            }
        }
    }

    // epilogue: atan2 + store
    const int hh = th * TH + pgh * 2;
    const int ww = tw * TW + pgw * 2;
    #pragma unroll
    for (int p = 0; p < 4; p++) {
        int h = hh + (p >> 1), w = ww + (p & 1);
        #pragma unroll
        for (int j = 0; j < 4; j++) {
            int co = cb + cg * 4 + j;
            out[((size_t)b * COUT + co) * HWHW + h * HW + w] =
                atan2f(accIm[p][j], accRe[p][j]);
        }
    }
}

extern "C" void kernel_launch(void* const* d_in, const int* in_sizes, int n_in,
                              void* d_out, int out_size) {
    const float* x     = (const float*)d_in[0];
    const float* probe = (const float*)d_in[1];
    const float* oang  = (const float*)d_in[2];
    float* out = (float*)d_out;

    {
        int n = CIN * COUT * KTAPS;
        prep_weights_kernel<<<(n + 255) / 256, 256>>>(probe, oang);
    }
    {
        int n = B_ * CIN * HWHW;
        prep_input_kernel<<<(n + 255) / 256, 256>>>(x);
    }
    {
        dim3 grid(49, COUT / COUT_T, B_);
        ring_conv_kernel<<<grid, NTHREADS>>>(out);
    }
}